// round 16
// baseline (speedup 1.0000x reference)
#include <cuda_runtime.h>
#include <cuda_fp16.h>
#include <cstdint>

// Problem constants
#define NTOK   4096
#define DM     1024
#define HID    4096
#define NEXP   8
#define NPAIRS (NTOK*2)      // 8192 (token, k) pairs

// ---------------- scratch (allocation-free __device__ globals) ----------------
__device__ __half g_w1h[(size_t)NEXP * HID * DM];   // fp16 w1
__device__ __half g_w2h[(size_t)NEXP * DM * HID];   // fp16 w2
__device__ __half g_xgh[(size_t)NPAIRS * DM];       // gathered activations (fp16)
__device__ __half g_h  [(size_t)NPAIRS * HID];      // hidden per slot (fp16)
__device__ float  g_y  [(size_t)NPAIRS * DM];       // expert outputs (fp32)
__device__ int    g_tok_e[NPAIRS];
__device__ float  g_tok_w[NPAIRS];
__device__ int    g_tok_slot[NPAIRS];
__device__ int    g_pair_tok[NPAIRS];
__device__ int    g_cnt[NEXP];
__device__ int    g_off[NEXP];
__device__ int    g_cur[NEXP];

// ---------------- portable PTX helpers ----------------
__device__ __forceinline__ uint32_t smem_u32(const void* p) {
    uint32_t a;
    asm("{ .reg .u64 t; cvta.to.shared.u64 t, %1; cvt.u32.u64 %0, t; }" : "=r"(a) : "l"(p));
    return a;
}
__device__ __forceinline__ void ldsm_x4(uint32_t* r, uint32_t addr) {
    asm volatile("ldmatrix.sync.aligned.m8n8.x4.shared.b16 {%0,%1,%2,%3}, [%4];"
        : "=r"(r[0]), "=r"(r[1]), "=r"(r[2]), "=r"(r[3]) : "r"(addr));
}
__device__ __forceinline__ void mma_f16(float* c, const uint32_t* a, const uint32_t* b) {
    asm volatile("mma.sync.aligned.m16n8k16.row.col.f32.f16.f16.f32 "
        "{%0,%1,%2,%3}, {%4,%5,%6,%7}, {%8,%9}, {%0,%1,%2,%3};"
        : "+f"(c[0]), "+f"(c[1]), "+f"(c[2]), "+f"(c[3])
        : "r"(a[0]), "r"(a[1]), "r"(a[2]), "r"(a[3]), "r"(b[0]), "r"(b[1]));
}
__device__ __forceinline__ void cp16(uint32_t saddr, const void* g, bool pred) {
    int sz = pred ? 16 : 0;
    asm volatile("cp.async.cg.shared.global [%0], [%1], 16, %2;"
                 :: "r"(saddr), "l"(g), "r"(sz));
}
#define CP_COMMIT() asm volatile("cp.async.commit_group;" ::: "memory")
#define CP_WAIT(n)  asm volatile("cp.async.wait_group %0;" :: "n"(n) : "memory")

// ---------------- routing kernels ----------------
__global__ void k_router(const float* __restrict__ x, const float* __restrict__ gw) {
    int t = (blockIdx.x * blockDim.x + threadIdx.x) >> 5;
    int lane = threadIdx.x & 31;
    if (t >= NTOK) return;
    const float4* xr = (const float4*)(x + (size_t)t * DM);
    const float4* g4 = (const float4*)gw;
    float s[NEXP];
    #pragma unroll
    for (int e = 0; e < NEXP; e++) s[e] = 0.f;
    #pragma unroll
    for (int j = 0; j < DM / 4 / 32; j++) {
        int idx = lane + j * 32;
        float4 xv = xr[idx];
        #pragma unroll
        for (int e = 0; e < NEXP; e++) {
            float4 wv = g4[e * (DM / 4) + idx];
            s[e] += xv.x * wv.x + xv.y * wv.y + xv.z * wv.z + xv.w * wv.w;
        }
    }
    #pragma unroll
    for (int e = 0; e < NEXP; e++)
        #pragma unroll
        for (int o = 16; o; o >>= 1) s[e] += __shfl_xor_sync(0xffffffffu, s[e], o);
    if (lane == 0) {
        float mx = s[0];
        #pragma unroll
        for (int e = 1; e < NEXP; e++) mx = fmaxf(mx, s[e]);
        float p[NEXP], den = 0.f;
        #pragma unroll
        for (int e = 0; e < NEXP; e++) { p[e] = expf(s[e] - mx); den += p[e]; }
        float inv = 1.f / den;
        int m0 = 0;
        #pragma unroll
        for (int e = 1; e < NEXP; e++) if (p[e] > p[m0]) m0 = e;
        int m1 = (m0 == 0) ? 1 : 0;
        #pragma unroll
        for (int e = 0; e < NEXP; e++) if (e != m0 && p[e] > p[m1]) m1 = e;
        g_tok_e[t * 2 + 0] = m0;  g_tok_e[t * 2 + 1] = m1;
        g_tok_w[t * 2 + 0] = p[m0] * inv;  g_tok_w[t * 2 + 1] = p[m1] * inv;
    }
}

__global__ void k_scan() {
    __shared__ int h[NEXP];
    int tid = threadIdx.x;
    if (tid < NEXP) h[tid] = 0;
    __syncthreads();
    for (int p = tid; p < NPAIRS; p += 256) atomicAdd(&h[g_tok_e[p]], 1);
    __syncthreads();
    if (tid == 0) {
        int acc = 0;
        for (int e = 0; e < NEXP; e++) {
            g_cnt[e] = h[e]; g_off[e] = acc; acc += h[e]; g_cur[e] = 0;
        }
    }
}

__global__ void k_slotgather(const float* __restrict__ x) {
    __shared__ int s_slot;
    int p = blockIdx.x;
    if (threadIdx.x == 0) {
        int e = g_tok_e[p];
        int slot = g_off[e] + atomicAdd(&g_cur[e], 1);
        g_pair_tok[slot] = p >> 1;
        g_tok_slot[p] = slot;
        s_slot = slot;
    }
    __syncthreads();
    int slot = s_slot;
    int d4 = threadIdx.x * 4;
    float4 v = *(const float4*)(x + (size_t)(p >> 1) * DM + d4);
    __half2 h[2] = {__floats2half2_rn(v.x, v.y), __floats2half2_rn(v.z, v.w)};
    *(uint2*)(g_xgh + (size_t)slot * DM + d4) = *(uint2*)h;
}

// fp32 -> fp16 weight conversion (grid covers n/8 elements)
__global__ void k_cvt(const float* __restrict__ src, __half* __restrict__ dst) {
    size_t i = ((size_t)blockIdx.x * blockDim.x + threadIdx.x) * 8;
    float4 f0 = *(const float4*)(src + i);
    float4 f1 = *(const float4*)(src + i + 4);
    __half2 h[4];
    h[0] = __floats2half2_rn(f0.x, f0.y);
    h[1] = __floats2half2_rn(f0.z, f0.w);
    h[2] = __floats2half2_rn(f1.x, f1.y);
    h[3] = __floats2half2_rn(f1.z, f1.w);
    *(uint4*)(dst + i) = *(uint4*)h;
}

// ---------------- fp16 mma.sync grouped GEMM (BK=32, frag-pipelined) ----------------
// CTA 128x128x32, 8 warps (2M x 4N), warp 64x32, occ 2.
// Fragments double-buffered across k16 sub-steps: ldsm for step s+1 issued before
// MMAs of step s, breaking the per-barrier LDSM/MMA phase convoy.
#define BM 128
#define BN 128
#define BK 32
#define ASTG 3
#define PITCH 80                          // 32 halves = 64B data + 16B pad
#define A_BYTES (BM * PITCH)              // 10240
#define B_BYTES (BN * PITCH)              // 10240
#define STG_B   (A_BYTES + B_BYTES)       // 20480
#define SM_TOTAL (ASTG * STG_B)           // 61440

template<int KTOT, bool RELU, typename OutT>
__global__ void __launch_bounds__(256, 2)
k_gemm(const __half* __restrict__ A,      // [slots, KTOT] fp16
       const __half* __restrict__ B,      // [NEXP*n_total, KTOT] fp16
       const float* __restrict__ bias,
       OutT* __restrict__ C,              // [slots, n_total]
       int n_total) {
    constexpr int NC = KTOT / BK;

    int e = blockIdx.z;
    int cnt = g_cnt[e];
    int m0 = blockIdx.y * BM;
    if (m0 >= cnt) return;
    int base = g_off[e];
    int n0 = blockIdx.x * BN;
    int mrem = cnt - m0;

    extern __shared__ char smc[];
    uint32_t sb = smem_u32(smc);
    int tid = threadIdx.x;
    int wid = tid >> 5, lane = tid & 31;
    int gp = lane >> 2, tg = lane & 3;
    int wm = (wid & 1) * 64;          // warp M offset
    int wn = (wid >> 1) * 32;         // warp N offset

    const __half* Ab = A + (size_t)(base + m0) * KTOT;
    const __half* Bb = B + ((size_t)e * n_total + n0) * KTOT;

    // loaders: A 512 16B tasks + B 512 tasks = 4 cp16/thread
    int r0t = tid >> 2, c0t = tid & 3;
    int r1t = (tid + 256) >> 2, c1t = (tid + 256) & 3;
    auto load_stage = [&](int c, int stg) {
        int k0 = c * BK;
        uint32_t as = sb + stg * STG_B;
        cp16(as + r0t * PITCH + c0t * 16, Ab + (size_t)r0t * KTOT + k0 + c0t * 8, r0t < mrem);
        cp16(as + r1t * PITCH + c1t * 16, Ab + (size_t)r1t * KTOT + k0 + c1t * 8, r1t < mrem);
        uint32_t bs = as + A_BYTES;
        cp16(bs + r0t * PITCH + c0t * 16, Bb + (size_t)r0t * KTOT + k0 + c0t * 8, true);
        cp16(bs + r1t * PITCH + c1t * 16, Bb + (size_t)r1t * KTOT + k0 + c1t * 8, true);
    };

    // per-lane ldmatrix offsets (k16 sub-step adds ks*32 bytes)
    int m4 = lane >> 3, ri = lane & 7;
    uint32_t a_off[4], b_off[2];
    #pragma unroll
    for (int mi = 0; mi < 4; mi++)
        a_off[mi] = (uint32_t)((wm + mi * 16 + (m4 & 1) * 8 + ri) * PITCH + (m4 >> 1) * 16);
    #pragma unroll
    for (int nj = 0; nj < 2; nj++)
        b_off[nj] = (uint32_t)(A_BYTES + (wn + nj * 16 + (m4 >> 1) * 8 + ri) * PITCH + (m4 & 1) * 16);

    float acc[4][4][4];
    #pragma unroll
    for (int i = 0; i < 4; i++)
        #pragma unroll
        for (int j = 0; j < 4; j++)
            #pragma unroll
            for (int q = 0; q < 4; q++) acc[i][j][q] = 0.f;

    // double-buffered fragments
    uint32_t af[2][4][4], bf[2][2][4];
    auto ldsm_step = [&](int b, uint32_t st, int ksoff) {
        #pragma unroll
        for (int mi = 0; mi < 4; mi++) ldsm_x4(af[b][mi], st + a_off[mi] + ksoff);
        #pragma unroll
        for (int nj = 0; nj < 2; nj++) ldsm_x4(bf[b][nj], st + b_off[nj] + ksoff);
    };
    auto mma_step = [&](int b) {
        #pragma unroll
        for (int mi = 0; mi < 4; mi++)
            #pragma unroll
            for (int ni = 0; ni < 4; ni++)
                mma_f16(acc[mi][ni], af[b][mi], &bf[b][ni >> 1][(ni & 1) * 2]);
    };

    // prologue: commit stages 0,1; ensure stage 0 arrived; commit stage 2; preload frags(0,0)
    load_stage(0, 0); CP_COMMIT();
    load_stage(1, 1); CP_COMMIT();
    CP_WAIT(ASTG - 2);
    __syncthreads();
    if (2 < NC) load_stage(2, 2);
    CP_COMMIT();
    ldsm_step(0, sb + 0 * STG_B, 0);

    #pragma unroll 1
    for (int c = 0; c < NC; c++) {
        uint32_t st = sb + (c % ASTG) * STG_B;
        ldsm_step(1, st, 32);              // prefetch (c, ks=1)
        mma_step(0);                       // compute (c, ks=0)
        if (c + 1 < NC) {
            CP_WAIT(ASTG - 2);             // stage c+1 arrived
            __syncthreads();               // all warps done reading stage c (ring slot reuse)
            if (c + 3 < NC) load_stage(c + 3, (c + 3) % ASTG);
            CP_COMMIT();
            ldsm_step(0, sb + ((c + 1) % ASTG) * STG_B, 0);  // prefetch (c+1, ks=0)
        }
        mma_step(1);                       // compute (c, ks=1)
    }

    // epilogue: bias (+relu), store
    const float* brow = bias + (size_t)e * n_total + n0;
    #pragma unroll
    for (int ni = 0; ni < 4; ni++) {
        int col = wn + ni * 8 + tg * 2;
        float b0 = brow[col], b1 = brow[col + 1];
        #pragma unroll
        for (int mi = 0; mi < 4; mi++) {
            int r0 = wm + mi * 16 + gp;
            float v0 = acc[mi][ni][0] + b0, v1 = acc[mi][ni][1] + b1;
            float v2 = acc[mi][ni][2] + b0, v3 = acc[mi][ni][3] + b1;
            if (RELU) {
                v0 = fmaxf(v0, 0.f); v1 = fmaxf(v1, 0.f);
                v2 = fmaxf(v2, 0.f); v3 = fmaxf(v3, 0.f);
            }
            if (r0 < mrem) {
                OutT* cr = C + (size_t)(base + m0 + r0) * n_total + n0 + col;
                if constexpr (sizeof(OutT) == 2) {
                    *(__half2*)cr = __floats2half2_rn(v0, v1);
                } else { cr[0] = v0; cr[1] = v1; }
            }
            if (r0 + 8 < mrem) {
                OutT* cr = C + (size_t)(base + m0 + r0 + 8) * n_total + n0 + col;
                if constexpr (sizeof(OutT) == 2) {
                    *(__half2*)cr = __floats2half2_rn(v2, v3);
                } else { cr[0] = v2; cr[1] = v3; }
            }
        }
    }
}

// out[t] = w0 * y[slot0] + w1 * y[slot1]
__global__ void k_combine(float* __restrict__ out) {
    int t = blockIdx.x;
    int d4 = threadIdx.x * 4;
    int s0 = g_tok_slot[t * 2 + 0], s1 = g_tok_slot[t * 2 + 1];
    float w0 = g_tok_w[t * 2 + 0],  w1 = g_tok_w[t * 2 + 1];
    float4 y0 = *(const float4*)(g_y + (size_t)s0 * DM + d4);
    float4 y1 = *(const float4*)(g_y + (size_t)s1 * DM + d4);
    float4 r;
    r.x = w0 * y0.x + w1 * y1.x;  r.y = w0 * y0.y + w1 * y1.y;
    r.z = w0 * y0.z + w1 * y1.z;  r.w = w0 * y0.w + w1 * y1.w;
    *(float4*)(out + (size_t)t * DM + d4) = r;
}

// ---------------- launch (graph-capturable two-stream fork) ----------------
extern "C" void kernel_launch(void* const* d_in, const int* in_sizes, int n_in,
                              void* d_out, int out_size) {
    const float* x  = (const float*)d_in[0];
    const float* gw = (const float*)d_in[1];
    const float* w1 = (const float*)d_in[2];
    const float* b1 = (const float*)d_in[3];
    const float* w2 = (const float*)d_in[4];
    const float* b2 = (const float*)d_in[5];
    float* out = (float*)d_out;

    static cudaStream_t s2 = nullptr;
    static cudaEvent_t ev_fork = nullptr, ev_w1 = nullptr, ev_w2 = nullptr;
    if (!s2) {
        cudaStreamCreateWithFlags(&s2, cudaStreamNonBlocking);
        cudaEventCreateWithFlags(&ev_fork, cudaEventDisableTiming);
        cudaEventCreateWithFlags(&ev_w1, cudaEventDisableTiming);
        cudaEventCreateWithFlags(&ev_w2, cudaEventDisableTiming);
        cudaFuncSetAttribute((const void*)k_gemm<DM, true, __half>,
                             cudaFuncAttributeMaxDynamicSharedMemorySize, SM_TOTAL);
        cudaFuncSetAttribute((const void*)k_gemm<HID, false, float>,
                             cudaFuncAttributeMaxDynamicSharedMemorySize, SM_TOTAL);
    }

    __half* w1h; cudaGetSymbolAddress((void**)&w1h, g_w1h);
    __half* w2h; cudaGetSymbolAddress((void**)&w2h, g_w2h);
    __half* xgh; cudaGetSymbolAddress((void**)&xgh, g_xgh);
    __half* hh;  cudaGetSymbolAddress((void**)&hh,  g_h);
    float*  yy;  cudaGetSymbolAddress((void**)&yy,  g_y);

    const size_t WN = (size_t)NEXP * HID * DM;
    const int CVT_GRID = (int)(WN / 8 / 256);

    // fork: s2 converts w1 while main stream runs the router chain
    cudaEventRecord(ev_fork, 0);
    cudaStreamWaitEvent(s2, ev_fork, 0);
    k_cvt<<<CVT_GRID, 256, 0, s2>>>(w1, w1h);
    cudaEventRecord(ev_w1, s2);

    k_router<<<NTOK / 8, 256>>>(x, gw);
    k_scan<<<1, 256>>>();
    k_slotgather<<<NPAIRS, 256>>>(x);

    // GEMM1 needs slotgather (main) + w1h (s2)
    cudaStreamWaitEvent(0, ev_w1, 0);
    k_gemm<DM, true, __half>
        <<<dim3(HID / BN, NPAIRS / BM, NEXP), 256, SM_TOTAL>>>(xgh, w1h, b1, hh, HID);

    // cvt(w2) on s2 runs concurrently with GEMM1
    k_cvt<<<CVT_GRID, 256, 0, s2>>>(w2, w2h);
    cudaEventRecord(ev_w2, s2);

    // GEMM2 needs g_h (main) + w2h (s2)
    cudaStreamWaitEvent(0, ev_w2, 0);
    k_gemm<HID, false, float>
        <<<dim3(DM / BN, NPAIRS / BM, NEXP), 256, SM_TOTAL>>>(hh, w2h, b2, yy, DM);
    k_combine<<<NTOK, 256>>>(out);
}

// round 17
// speedup vs baseline: 1.1143x; 1.1143x over previous
#include <cuda_runtime.h>
#include <cuda_fp16.h>
#include <cstdint>

// Problem constants
#define NTOK   4096
#define DM     1024
#define HID    4096
#define NEXP   8
#define NPAIRS (NTOK*2)      // 8192 (token, k) pairs

// ---------------- scratch (allocation-free __device__ globals) ----------------
__device__ __half g_w1h[(size_t)NEXP * HID * DM];   // fp16 w1
__device__ __half g_w2h[(size_t)NEXP * DM * HID];   // fp16 w2
__device__ __half g_xgh[(size_t)NPAIRS * DM];       // gathered activations (fp16)
__device__ __half g_h  [(size_t)NPAIRS * HID];      // hidden per slot (fp16)
__device__ float  g_y  [(size_t)NPAIRS * DM];       // expert outputs (fp32)
__device__ int    g_tok_e[NPAIRS];
__device__ float  g_tok_w[NPAIRS];
__device__ int    g_tok_slot[NPAIRS];
__device__ int    g_pair_tok[NPAIRS];
__device__ int    g_cnt[NEXP];
__device__ int    g_off[NEXP];
__device__ int    g_cur[NEXP];

// ---------------- portable PTX helpers ----------------
__device__ __forceinline__ uint32_t smem_u32(const void* p) {
    uint32_t a;
    asm("{ .reg .u64 t; cvta.to.shared.u64 t, %1; cvt.u32.u64 %0, t; }" : "=r"(a) : "l"(p));
    return a;
}
__device__ __forceinline__ void ldsm_x4(uint32_t* r, uint32_t addr) {
    asm volatile("ldmatrix.sync.aligned.m8n8.x4.shared.b16 {%0,%1,%2,%3}, [%4];"
        : "=r"(r[0]), "=r"(r[1]), "=r"(r[2]), "=r"(r[3]) : "r"(addr));
}
__device__ __forceinline__ void mma_f16(float* c, const uint32_t* a, const uint32_t* b) {
    asm volatile("mma.sync.aligned.m16n8k16.row.col.f32.f16.f16.f32 "
        "{%0,%1,%2,%3}, {%4,%5,%6,%7}, {%8,%9}, {%0,%1,%2,%3};"
        : "+f"(c[0]), "+f"(c[1]), "+f"(c[2]), "+f"(c[3])
        : "r"(a[0]), "r"(a[1]), "r"(a[2]), "r"(a[3]), "r"(b[0]), "r"(b[1]));
}
__device__ __forceinline__ void cp16(uint32_t saddr, const void* g, bool pred) {
    int sz = pred ? 16 : 0;
    asm volatile("cp.async.cg.shared.global [%0], [%1], 16, %2;"
                 :: "r"(saddr), "l"(g), "r"(sz));
}
#define CP_COMMIT() asm volatile("cp.async.commit_group;" ::: "memory")
#define CP_WAIT(n)  asm volatile("cp.async.wait_group %0;" :: "n"(n) : "memory")

// ---------------- routing kernels ----------------
// 4 tokens per warp: expert weights loaded once per j, reused across 4 tokens
__global__ void k_router(const float* __restrict__ x, const float* __restrict__ gw) {
    int w = (blockIdx.x * blockDim.x + threadIdx.x) >> 5;
    int lane = threadIdx.x & 31;
    int t0 = w * 4;
    if (t0 >= NTOK) return;
    const float4* g4 = (const float4*)gw;

    float s[4][NEXP];
    #pragma unroll
    for (int ti = 0; ti < 4; ti++)
        #pragma unroll
        for (int e = 0; e < NEXP; e++) s[ti][e] = 0.f;

    #pragma unroll
    for (int j = 0; j < DM / 4 / 32; j++) {
        int idx = lane + j * 32;
        float4 wv[NEXP];
        #pragma unroll
        for (int e = 0; e < NEXP; e++) wv[e] = g4[e * (DM / 4) + idx];
        #pragma unroll
        for (int ti = 0; ti < 4; ti++) {
            float4 xv = ((const float4*)(x + (size_t)(t0 + ti) * DM))[idx];
            #pragma unroll
            for (int e = 0; e < NEXP; e++)
                s[ti][e] += xv.x * wv[e].x + xv.y * wv[e].y + xv.z * wv[e].z + xv.w * wv[e].w;
        }
    }
    #pragma unroll
    for (int ti = 0; ti < 4; ti++)
        #pragma unroll
        for (int e = 0; e < NEXP; e++)
            #pragma unroll
            for (int o = 16; o; o >>= 1) s[ti][e] += __shfl_xor_sync(0xffffffffu, s[ti][e], o);

    if (lane == 0) {
        #pragma unroll
        for (int ti = 0; ti < 4; ti++) {
            int t = t0 + ti;
            float mx = s[ti][0];
            #pragma unroll
            for (int e = 1; e < NEXP; e++) mx = fmaxf(mx, s[ti][e]);
            float p[NEXP], den = 0.f;
            #pragma unroll
            for (int e = 0; e < NEXP; e++) { p[e] = expf(s[ti][e] - mx); den += p[e]; }
            float inv = 1.f / den;
            int m0 = 0;
            #pragma unroll
            for (int e = 1; e < NEXP; e++) if (p[e] > p[m0]) m0 = e;
            int m1 = (m0 == 0) ? 1 : 0;
            #pragma unroll
            for (int e = 0; e < NEXP; e++) if (e != m0 && p[e] > p[m1]) m1 = e;
            g_tok_e[t * 2 + 0] = m0;  g_tok_e[t * 2 + 1] = m1;
            g_tok_w[t * 2 + 0] = p[m0] * inv;  g_tok_w[t * 2 + 1] = p[m1] * inv;
        }
    }
}

__global__ void k_scan() {
    __shared__ int h[NEXP];
    int tid = threadIdx.x;
    if (tid < NEXP) h[tid] = 0;
    __syncthreads();
    for (int p = tid; p < NPAIRS; p += 256) atomicAdd(&h[g_tok_e[p]], 1);
    __syncthreads();
    if (tid == 0) {
        int acc = 0;
        for (int e = 0; e < NEXP; e++) {
            g_cnt[e] = h[e]; g_off[e] = acc; acc += h[e]; g_cur[e] = 0;
        }
    }
}

__global__ void k_slotgather(const float* __restrict__ x) {
    __shared__ int s_slot;
    int p = blockIdx.x;
    if (threadIdx.x == 0) {
        int e = g_tok_e[p];
        int slot = g_off[e] + atomicAdd(&g_cur[e], 1);
        g_pair_tok[slot] = p >> 1;
        g_tok_slot[p] = slot;
        s_slot = slot;
    }
    __syncthreads();
    int slot = s_slot;
    int d4 = threadIdx.x * 4;
    float4 v = *(const float4*)(x + (size_t)(p >> 1) * DM + d4);
    __half2 h[2] = {__floats2half2_rn(v.x, v.y), __floats2half2_rn(v.z, v.w)};
    *(uint2*)(g_xgh + (size_t)slot * DM + d4) = *(uint2*)h;
}

// fp32 -> fp16 weight conversion (grid covers n/8 elements)
__global__ void k_cvt(const float* __restrict__ src, __half* __restrict__ dst) {
    size_t i = ((size_t)blockIdx.x * blockDim.x + threadIdx.x) * 8;
    float4 f0 = *(const float4*)(src + i);
    float4 f1 = *(const float4*)(src + i + 4);
    __half2 h[4];
    h[0] = __floats2half2_rn(f0.x, f0.y);
    h[1] = __floats2half2_rn(f0.z, f0.w);
    h[2] = __floats2half2_rn(f1.x, f1.y);
    h[3] = __floats2half2_rn(f1.z, f1.w);
    *(uint4*)(dst + i) = *(uint4*)h;
}

// ---------------- fp16 mma.sync grouped GEMM (BK=64, all-fp16 cp.async) ----------------
// CTA 128x128x64, 8 warps (2M x 4N), warp 64x32, occ 2, 3-stage ring.
#define BM 128
#define BN 128
#define BK 64
#define ASTG 3
#define PITCH 144                         // 64 halves = 128B data + 16B pad
#define A_BYTES (BM * PITCH)              // 18432
#define B_BYTES (BN * PITCH)              // 18432
#define STG_B   (A_BYTES + B_BYTES)       // 36864
#define SM_TOTAL (ASTG * STG_B)           // 110592

template<int KTOT, bool RELU, typename OutT>
__global__ void __launch_bounds__(256, 2)
k_gemm(const __half* __restrict__ A,      // [slots, KTOT] fp16
       const __half* __restrict__ B,      // [NEXP*n_total, KTOT] fp16
       const float* __restrict__ bias,
       OutT* __restrict__ C,              // [slots, n_total]
       int n_total) {
    constexpr int NC = KTOT / BK;

    int e = blockIdx.z;
    int cnt = g_cnt[e];
    int m0 = blockIdx.y * BM;
    if (m0 >= cnt) return;
    int base = g_off[e];
    int n0 = blockIdx.x * BN;
    int mrem = cnt - m0;

    extern __shared__ char smc[];
    uint32_t sb = smem_u32(smc);
    int tid = threadIdx.x;
    int wid = tid >> 5, lane = tid & 31;
    int gp = lane >> 2, tg = lane & 3;
    int wm = (wid & 1) * 64;          // warp M offset
    int wn = (wid >> 1) * 32;         // warp N offset

    const __half* Ab = A + (size_t)(base + m0) * KTOT;
    const __half* Bb = B + ((size_t)e * n_total + n0) * KTOT;

    // loaders: A 1024 16B tasks + B 1024 tasks = 8 cp16/thread
    // task t: row = t>>3 (128 rows), chunk = t&7 (8 x 16B = 128B)
    auto load_stage = [&](int c, int stg) {
        int k0 = c * BK;
        uint32_t as = sb + stg * STG_B;
        uint32_t bs = as + A_BYTES;
        #pragma unroll
        for (int i = 0; i < 4; i++) {
            int t = tid + i * 256;
            int r = t >> 3, ch = t & 7;
            cp16(as + r * PITCH + ch * 16, Ab + (size_t)r * KTOT + k0 + ch * 8, r < mrem);
            cp16(bs + r * PITCH + ch * 16, Bb + (size_t)r * KTOT + k0 + ch * 8, true);
        }
    };

    // per-lane ldmatrix offsets (k16 sub-step adds ks*32 bytes)
    int m4 = lane >> 3, ri = lane & 7;
    uint32_t a_off[4], b_off[2];
    #pragma unroll
    for (int mi = 0; mi < 4; mi++)
        a_off[mi] = (uint32_t)((wm + mi * 16 + (m4 & 1) * 8 + ri) * PITCH + (m4 >> 1) * 16);
    #pragma unroll
    for (int nj = 0; nj < 2; nj++)
        b_off[nj] = (uint32_t)(A_BYTES + (wn + nj * 16 + (m4 >> 1) * 8 + ri) * PITCH + (m4 & 1) * 16);

    float acc[4][4][4];
    #pragma unroll
    for (int i = 0; i < 4; i++)
        #pragma unroll
        for (int j = 0; j < 4; j++)
            #pragma unroll
            for (int q = 0; q < 4; q++) acc[i][j][q] = 0.f;

    #pragma unroll
    for (int s = 0; s < ASTG - 1; s++) { load_stage(s, s); CP_COMMIT(); }

    #pragma unroll 1
    for (int c = 0; c < NC; c++) {
        CP_WAIT(ASTG - 2);
        __syncthreads();

        if (c + ASTG - 1 < NC) load_stage(c + ASTG - 1, (c + ASTG - 1) % ASTG);
        CP_COMMIT();

        uint32_t st = sb + (c % ASTG) * STG_B;

        #pragma unroll
        for (int ks = 0; ks < 4; ks++) {       // four k16 sub-steps
            uint32_t af[4][4], bf[2][4];
            #pragma unroll
            for (int mi = 0; mi < 4; mi++) ldsm_x4(af[mi], st + a_off[mi] + ks * 32);
            #pragma unroll
            for (int nj = 0; nj < 2; nj++) ldsm_x4(bf[nj], st + b_off[nj] + ks * 32);
            #pragma unroll
            for (int mi = 0; mi < 4; mi++)
                #pragma unroll
                for (int ni = 0; ni < 4; ni++)
                    mma_f16(acc[mi][ni], af[mi], &bf[ni >> 1][(ni & 1) * 2]);
        }
    }

    // epilogue: bias (+relu), store
    const float* brow = bias + (size_t)e * n_total + n0;
    #pragma unroll
    for (int ni = 0; ni < 4; ni++) {
        int col = wn + ni * 8 + tg * 2;
        float b0 = brow[col], b1 = brow[col + 1];
        #pragma unroll
        for (int mi = 0; mi < 4; mi++) {
            int r0 = wm + mi * 16 + gp;
            float v0 = acc[mi][ni][0] + b0, v1 = acc[mi][ni][1] + b1;
            float v2 = acc[mi][ni][2] + b0, v3 = acc[mi][ni][3] + b1;
            if (RELU) {
                v0 = fmaxf(v0, 0.f); v1 = fmaxf(v1, 0.f);
                v2 = fmaxf(v2, 0.f); v3 = fmaxf(v3, 0.f);
            }
            if (r0 < mrem) {
                OutT* cr = C + (size_t)(base + m0 + r0) * n_total + n0 + col;
                if constexpr (sizeof(OutT) == 2) {
                    *(__half2*)cr = __floats2half2_rn(v0, v1);
                } else { cr[0] = v0; cr[1] = v1; }
            }
            if (r0 + 8 < mrem) {
                OutT* cr = C + (size_t)(base + m0 + r0 + 8) * n_total + n0 + col;
                if constexpr (sizeof(OutT) == 2) {
                    *(__half2*)cr = __floats2half2_rn(v2, v3);
                } else { cr[0] = v2; cr[1] = v3; }
            }
        }
    }
}

// out[t] = w0 * y[slot0] + w1 * y[slot1]
__global__ void k_combine(float* __restrict__ out) {
    int t = blockIdx.x;
    int d4 = threadIdx.x * 4;
    int s0 = g_tok_slot[t * 2 + 0], s1 = g_tok_slot[t * 2 + 1];
    float w0 = g_tok_w[t * 2 + 0],  w1 = g_tok_w[t * 2 + 1];
    float4 y0 = *(const float4*)(g_y + (size_t)s0 * DM + d4);
    float4 y1 = *(const float4*)(g_y + (size_t)s1 * DM + d4);
    float4 r;
    r.x = w0 * y0.x + w1 * y1.x;  r.y = w0 * y0.y + w1 * y1.y;
    r.z = w0 * y0.z + w1 * y1.z;  r.w = w0 * y0.w + w1 * y1.w;
    *(float4*)(out + (size_t)t * DM + d4) = r;
}

// ---------------- launch (graph-capturable two-stream fork) ----------------
extern "C" void kernel_launch(void* const* d_in, const int* in_sizes, int n_in,
                              void* d_out, int out_size) {
    const float* x  = (const float*)d_in[0];
    const float* gw = (const float*)d_in[1];
    const float* w1 = (const float*)d_in[2];
    const float* b1 = (const float*)d_in[3];
    const float* w2 = (const float*)d_in[4];
    const float* b2 = (const float*)d_in[5];
    float* out = (float*)d_out;

    static cudaStream_t s2 = nullptr;
    static cudaEvent_t ev_fork = nullptr, ev_w1 = nullptr, ev_w2 = nullptr;
    if (!s2) {
        cudaStreamCreateWithFlags(&s2, cudaStreamNonBlocking);
        cudaEventCreateWithFlags(&ev_fork, cudaEventDisableTiming);
        cudaEventCreateWithFlags(&ev_w1, cudaEventDisableTiming);
        cudaEventCreateWithFlags(&ev_w2, cudaEventDisableTiming);
        cudaFuncSetAttribute((const void*)k_gemm<DM, true, __half>,
                             cudaFuncAttributeMaxDynamicSharedMemorySize, SM_TOTAL);
        cudaFuncSetAttribute((const void*)k_gemm<HID, false, float>,
                             cudaFuncAttributeMaxDynamicSharedMemorySize, SM_TOTAL);
    }

    __half* w1h; cudaGetSymbolAddress((void**)&w1h, g_w1h);
    __half* w2h; cudaGetSymbolAddress((void**)&w2h, g_w2h);
    __half* xgh; cudaGetSymbolAddress((void**)&xgh, g_xgh);
    __half* hh;  cudaGetSymbolAddress((void**)&hh,  g_h);
    float*  yy;  cudaGetSymbolAddress((void**)&yy,  g_y);

    const size_t WN = (size_t)NEXP * HID * DM;
    const int CVT_GRID = (int)(WN / 8 / 256);

    // fork: s2 converts w1 while main stream runs the router chain
    cudaEventRecord(ev_fork, 0);
    cudaStreamWaitEvent(s2, ev_fork, 0);
    k_cvt<<<CVT_GRID, 256, 0, s2>>>(w1, w1h);
    cudaEventRecord(ev_w1, s2);

    k_router<<<NTOK / 4 / 8, 256>>>(x, gw);   // 4 tokens/warp, 8 warps/block
    k_scan<<<1, 256>>>();
    k_slotgather<<<NPAIRS, 256>>>(x);

    // GEMM1 needs slotgather (main) + w1h (s2)
    cudaStreamWaitEvent(0, ev_w1, 0);
    k_gemm<DM, true, __half>
        <<<dim3(HID / BN, NPAIRS / BM, NEXP), 256, SM_TOTAL>>>(xgh, w1h, b1, hh, HID);

    // cvt(w2) on s2 runs concurrently with GEMM1
    k_cvt<<<CVT_GRID, 256, 0, s2>>>(w2, w2h);
    cudaEventRecord(ev_w2, s2);

    // GEMM2 needs g_h (main) + w2h (s2)
    cudaStreamWaitEvent(0, ev_w2, 0);
    k_gemm<HID, false, float>
        <<<dim3(DM / BN, NPAIRS / BM, NEXP), 256, SM_TOTAL>>>(hh, w2h, b2, yy, DM);
    k_combine<<<NTOK, 256>>>(out);
}